// round 2
// baseline (speedup 1.0000x reference)
#include <cuda_runtime.h>
#include <math.h>

#define NBINS 15
#define C_DIM 1000
#define C4    250          // float4 per row
#define WARPS_PER_BLOCK 8
#define THREADS (WARPS_PER_BLOCK * 32)
#define GRID_BLOCKS 1024

// Global accumulators (allocation-free scratch).
__device__ double g_cnt[NBINS];
__device__ double g_conf[NBINS];
__device__ double g_acc[NBINS];

__global__ void ece_zero_kernel() {
    int i = threadIdx.x;
    if (i < NBINS) {
        g_cnt[i]  = 0.0;
        g_conf[i] = 0.0;
        g_acc[i]  = 0.0;
    }
}

__global__ __launch_bounds__(THREADS) void ece_main_kernel(
    const float* __restrict__ logits,
    const int* __restrict__ labels,   // JAX w/o x64 downcasts int64 -> int32
    int n_rows)
{
    __shared__ float s_cnt[NBINS];
    __shared__ float s_conf[NBINS];
    __shared__ float s_acc[NBINS];

    const int tid  = threadIdx.x;
    const int lane = tid & 31;
    const int warp = tid >> 5;

    if (tid < NBINS) {
        s_cnt[tid]  = 0.0f;
        s_conf[tid] = 0.0f;
        s_acc[tid]  = 0.0f;
    }
    __syncthreads();

    const int total_warps = gridDim.x * WARPS_PER_BLOCK;
    const int warp_global = blockIdx.x * WARPS_PER_BLOCK + warp;

    for (int row = warp_global; row < n_rows; row += total_warps) {
        const float4* rp = reinterpret_cast<const float4*>(logits + (size_t)row * C_DIM);

        // Front-batched vectorized loads: 8 independent float4 per lane (MLP=8).
        float4 v[8];
        #pragma unroll
        for (int k = 0; k < 8; k++) {
            int c4 = lane + 32 * k;
            if (c4 < C4) {
                v[k] = rp[c4];
            } else {
                v[k] = make_float4(-1e30f, -1e30f, -1e30f, -1e30f);
            }
        }

        // Pass 1 (registers): per-lane max + argmax (first occurrence via strict >).
        float m = -1e30f;
        int   mi = 0x7fffffff;
        #pragma unroll
        for (int k = 0; k < 8; k++) {
            int base = 4 * (lane + 32 * k);
            float4 x = v[k];
            if (x.x > m) { m = x.x; mi = base;     }
            if (x.y > m) { m = x.y; mi = base + 1; }
            if (x.z > m) { m = x.z; mi = base + 2; }
            if (x.w > m) { m = x.w; mi = base + 3; }
        }
        // Warp bfly reduce (max, idx); ties -> smaller index (first occurrence).
        #pragma unroll
        for (int off = 16; off; off >>= 1) {
            float om = __shfl_xor_sync(0xffffffffu, m,  off);
            int   oi = __shfl_xor_sync(0xffffffffu, mi, off);
            if (om > m || (om == m && oi < mi)) { m = om; mi = oi; }
        }

        // Pass 2 (registers): sum of exp(x - m). Padding (-1e30) underflows to 0.
        float s = 0.0f;
        #pragma unroll
        for (int k = 0; k < 8; k++) {
            float4 x = v[k];
            s += __expf(x.x - m) + __expf(x.y - m)
               + __expf(x.z - m) + __expf(x.w - m);
        }
        #pragma unroll
        for (int off = 16; off; off >>= 1) {
            s += __shfl_xor_sync(0xffffffffu, s, off);
        }

        if (lane == 0) {
            // confidence = exp(m - lse) = 1 / sum_i exp(x_i - m)
            float conf = 1.0f / s;
            // bin i covers (i/15, (i+1)/15]; conf > 0 always so bin >= 0, valid=1.
            int bin = 0;
            #pragma unroll
            for (int i = 1; i < NBINS; i++) {
                bin += (conf > ((float)i / (float)NBINS)) ? 1 : 0;
            }
            float acc = (labels[row] == mi) ? 1.0f : 0.0f;
            atomicAdd(&s_cnt[bin],  1.0f);
            atomicAdd(&s_conf[bin], conf);
            atomicAdd(&s_acc[bin],  acc);
        }
    }

    __syncthreads();
    if (tid < NBINS) {
        float c = s_cnt[tid];
        if (c != 0.0f) {
            atomicAdd(&g_cnt[tid],  (double)c);
            atomicAdd(&g_conf[tid], (double)s_conf[tid]);
            atomicAdd(&g_acc[tid],  (double)s_acc[tid]);
        }
    }
}

__global__ void ece_finalize_kernel(float* __restrict__ out, int n_rows) {
    if (threadIdx.x == 0 && blockIdx.x == 0) {
        double inv_n = 1.0 / (double)n_rows;
        double ece = 0.0, accv = 0.0;
        #pragma unroll
        for (int i = 0; i < NBINS; i++) {
            double cnt = g_cnt[i];
            if (cnt > 0.0) {
                double prop = cnt * inv_n;
                double avg_conf = g_conf[i] / cnt;
                double avg_acc  = g_acc[i]  / cnt;
                ece  += fabs(avg_conf - avg_acc) * prop;
                accv += avg_acc * prop;
            }
        }
        out[0] = (float)(ece  * 100.0);
        out[1] = (float)(accv * 100.0);
    }
}

extern "C" void kernel_launch(void* const* d_in, const int* in_sizes, int n_in,
                              void* d_out, int out_size) {
    const float* logits = (const float*)d_in[0];
    const int*   labels = (const int*)d_in[1];
    float* out = (float*)d_out;

    int n_rows = in_sizes[1];  // labels element count = N

    ece_zero_kernel<<<1, 32>>>();
    ece_main_kernel<<<GRID_BLOCKS, THREADS>>>(logits, labels, n_rows);
    ece_finalize_kernel<<<1, 32>>>(out, n_rows);
}

// round 3
// speedup vs baseline: 1.0880x; 1.0880x over previous
#include <cuda_runtime.h>
#include <math.h>

#define NBINS 15
#define C_DIM 1000
#define C4    250          // float4 per row
#define WARPS_PER_BLOCK 8
#define THREADS (WARPS_PER_BLOCK * 32)
#define GRID_BLOCKS 608    // 152 SMs x 4 blocks: exact single wave

// Global accumulators (allocation-free scratch). Zero at module load for the
// first (correctness) call; the finishing block resets them for every
// subsequent graph replay.
__device__ double g_cnt[NBINS];
__device__ double g_conf[NBINS];
__device__ double g_acc[NBINS];
__device__ unsigned int g_ticket = 0;

__global__ __launch_bounds__(THREADS, 4) void ece_fused_kernel(
    const float* __restrict__ logits,
    const int* __restrict__ labels,
    int n_rows,
    float* __restrict__ out)
{
    __shared__ float s_cnt[NBINS];
    __shared__ float s_conf[NBINS];
    __shared__ float s_acc[NBINS];
    __shared__ bool  s_is_last;

    const int tid  = threadIdx.x;
    const int lane = tid & 31;
    const int warp = tid >> 5;

    if (tid < NBINS) {
        s_cnt[tid]  = 0.0f;
        s_conf[tid] = 0.0f;
        s_acc[tid]  = 0.0f;
    }
    __syncthreads();

    const int total_warps = gridDim.x * WARPS_PER_BLOCK;
    const int warp_global = blockIdx.x * WARPS_PER_BLOCK + warp;

    for (int row = warp_global; row < n_rows; row += total_warps) {
        const float4* rp = reinterpret_cast<const float4*>(logits + (size_t)row * C_DIM);

        // Front-batched vectorized loads: 8 independent float4 per lane (MLP=8).
        float4 v[8];
        #pragma unroll
        for (int k = 0; k < 8; k++) {
            int c4 = lane + 32 * k;
            if (c4 < C4) {
                v[k] = rp[c4];
            } else {
                v[k] = make_float4(-1e30f, -1e30f, -1e30f, -1e30f);
            }
        }

        // Pass 1 (registers): per-lane max + argmax (first occurrence via strict >).
        float m = -1e30f;
        int   mi = 0x7fffffff;
        #pragma unroll
        for (int k = 0; k < 8; k++) {
            int base = 4 * (lane + 32 * k);
            float4 x = v[k];
            if (x.x > m) { m = x.x; mi = base;     }
            if (x.y > m) { m = x.y; mi = base + 1; }
            if (x.z > m) { m = x.z; mi = base + 2; }
            if (x.w > m) { m = x.w; mi = base + 3; }
        }
        // Warp bfly reduce (max, idx); ties -> smaller index (first occurrence).
        #pragma unroll
        for (int off = 16; off; off >>= 1) {
            float om = __shfl_xor_sync(0xffffffffu, m,  off);
            int   oi = __shfl_xor_sync(0xffffffffu, mi, off);
            if (om > m || (om == m && oi < mi)) { m = om; mi = oi; }
        }

        // Pass 2 (registers): sum of exp(x - m). Padding (-1e30) underflows to 0.
        float s = 0.0f;
        #pragma unroll
        for (int k = 0; k < 8; k++) {
            float4 x = v[k];
            s += __expf(x.x - m) + __expf(x.y - m)
               + __expf(x.z - m) + __expf(x.w - m);
        }
        #pragma unroll
        for (int off = 16; off; off >>= 1) {
            s += __shfl_xor_sync(0xffffffffu, s, off);
        }

        if (lane == 0) {
            // confidence = exp(m - lse) = 1 / sum_i exp(x_i - m)
            float conf = 1.0f / s;
            // bin i covers (i/15, (i+1)/15]; conf > 0 always so bin >= 0, valid=1.
            int bin = 0;
            #pragma unroll
            for (int i = 1; i < NBINS; i++) {
                bin += (conf > ((float)i / (float)NBINS)) ? 1 : 0;
            }
            float acc = (labels[row] == mi) ? 1.0f : 0.0f;
            atomicAdd(&s_cnt[bin],  1.0f);
            atomicAdd(&s_conf[bin], conf);
            atomicAdd(&s_acc[bin],  acc);
        }
    }

    __syncthreads();
    if (tid < NBINS) {
        float c = s_cnt[tid];
        if (c != 0.0f) {
            atomicAdd(&g_cnt[tid],  (double)c);
            atomicAdd(&g_conf[tid], (double)s_conf[tid]);
            atomicAdd(&g_acc[tid],  (double)s_acc[tid]);
        }
    }

    // Last-block-done: fence our global atomics, then take a ticket.
    __threadfence();
    __syncthreads();
    if (tid == 0) {
        unsigned int t = atomicAdd(&g_ticket, 1u);
        s_is_last = (t == gridDim.x - 1);
    }
    __syncthreads();

    if (s_is_last && warp == 0) {
        // Finalize: lanes 0..14 each handle one bin, then butterfly-sum.
        double term_ece = 0.0, term_acc = 0.0;
        if (lane < NBINS) {
            double cnt = g_cnt[lane];
            if (cnt > 0.0) {
                double prop = cnt / (double)n_rows;
                double avg_conf = g_conf[lane] / cnt;
                double avg_acc  = g_acc[lane]  / cnt;
                term_ece = fabs(avg_conf - avg_acc) * prop;
                term_acc = avg_acc * prop;
            }
            // Reset accumulators for the next graph replay.
            g_cnt[lane]  = 0.0;
            g_conf[lane] = 0.0;
            g_acc[lane]  = 0.0;
        }
        #pragma unroll
        for (int off = 16; off; off >>= 1) {
            term_ece += __shfl_xor_sync(0xffffffffu, term_ece, off);
            term_acc += __shfl_xor_sync(0xffffffffu, term_acc, off);
        }
        if (lane == 0) {
            out[0] = (float)(term_ece * 100.0);
            out[1] = (float)(term_acc * 100.0);
            g_ticket = 0;
        }
    }
}

extern "C" void kernel_launch(void* const* d_in, const int* in_sizes, int n_in,
                              void* d_out, int out_size) {
    const float* logits = (const float*)d_in[0];
    const int*   labels = (const int*)d_in[1];
    float* out = (float*)d_out;

    int n_rows = in_sizes[1];  // labels element count = N

    ece_fused_kernel<<<GRID_BLOCKS, THREADS>>>(logits, labels, n_rows, out);
}

// round 4
// speedup vs baseline: 1.1158x; 1.0256x over previous
#include <cuda_runtime.h>
#include <math.h>

#define NBINS 15
#define C_DIM 1000
#define C4    250          // float4 per row
#define WARPS_PER_BLOCK 8
#define THREADS (WARPS_PER_BLOCK * 32)
#define GRID_BLOCKS 304    // 152 SMs x 2 blocks resident: persistent single wave

// Global accumulators (allocation-free scratch). Zeroed at module load for the
// first (correctness) call; the finishing block resets them for each replay.
__device__ double g_cnt[NBINS];
__device__ double g_conf[NBINS];
__device__ double g_acc[NBINS];
__device__ unsigned int g_ticket = 0;

__device__ __forceinline__ float ex2f(float x) {
    float r;
    asm("ex2.approx.f32 %0, %1;" : "=f"(r) : "f"(x));
    return r;
}

// Order-preserving float -> uint (for integer max-redux), and inverse.
__device__ __forceinline__ unsigned f2ord(float f) {
    int i = __float_as_int(f);
    return (unsigned)(i ^ ((i >> 31) | 0x80000000));
}
__device__ __forceinline__ float ord2f(unsigned u) {
    int i = (int)(u ^ ((((int)~u) >> 31) | 0x80000000));
    return __int_as_float(i);
}

__device__ __forceinline__ void load_row(float4 (&v)[8],
                                         const float* __restrict__ logits,
                                         int row, int lane) {
    const float4* rp = reinterpret_cast<const float4*>(logits + (size_t)row * C_DIM) + lane;
    #pragma unroll
    for (int k = 0; k < 8; k++) {
        if (lane + 32 * k < C4) {
            v[k] = rp[32 * k];
        } else {
            v[k] = make_float4(-1e30f, -1e30f, -1e30f, -1e30f);
        }
    }
}

__device__ __forceinline__ void process_row(const float4 (&v)[8],
                                            const int* __restrict__ labels,
                                            int row, int lane,
                                            float* s_cnt, float* s_conf, float* s_acc) {
    // Per-float4 maxes (1 FMNMX/elem total), then tree to per-lane max.
    float m4[8];
    #pragma unroll
    for (int k = 0; k < 8; k++)
        m4[k] = fmaxf(fmaxf(v[k].x, v[k].y), fmaxf(v[k].z, v[k].w));
    float a0 = fmaxf(m4[0], m4[1]);
    float a1 = fmaxf(m4[2], m4[3]);
    float a2 = fmaxf(m4[4], m4[5]);
    float a3 = fmaxf(m4[6], m4[7]);
    float m  = fmaxf(fmaxf(a0, a1), fmaxf(a2, a3));

    // Warp max via integer redux on order-preserving key.
    unsigned wkey = __reduce_max_sync(0xffffffffu, f2ord(m));
    float wm = ord2f(wkey);

    // Argmax drill-down (per-row cost only): smallest index holding wm.
    int mi = 0x7fffffff;
    #pragma unroll
    for (int k = 7; k >= 0; k--) {
        if (m4[k] == wm) {
            int base = 4 * (lane + 32 * k);
            if (v[k].w == wm) mi = base + 3;
            if (v[k].z == wm) mi = base + 2;
            if (v[k].y == wm) mi = base + 1;
            if (v[k].x == wm) mi = base;
        }
    }
    unsigned wmi = __reduce_min_sync(0xffffffffu, (unsigned)mi);

    // Sum of exp(x - wm) = 2^(x*log2e - wm*log2e): FFMA + MUFU per elem,
    // 4 accumulators break the serial add chain. Padding (-1e30) -> 2^-inf = 0.
    const float L = 1.4426950408889634f;
    const float b = -wm * L;
    float s0 = 0.f, s1 = 0.f, s2 = 0.f, s3 = 0.f;
    #pragma unroll
    for (int k = 0; k < 8; k++) {
        s0 += ex2f(fmaf(v[k].x, L, b));
        s1 += ex2f(fmaf(v[k].y, L, b));
        s2 += ex2f(fmaf(v[k].z, L, b));
        s3 += ex2f(fmaf(v[k].w, L, b));
    }
    float s = (s0 + s1) + (s2 + s3);
    #pragma unroll
    for (int off = 16; off; off >>= 1)
        s += __shfl_xor_sync(0xffffffffu, s, off);

    if (lane == 0) {
        // confidence = exp(wm - lse) = 1 / sum exp(x - wm); conf > 0 so valid=1.
        float conf = 1.0f / s;
        // bin i covers (i/15, (i+1)/15]: count of lowers strictly below conf, -1.
        int bin = 0;
        #pragma unroll
        for (int i = 1; i < NBINS; i++)
            bin += (conf > ((float)i / (float)NBINS)) ? 1 : 0;
        float acc = (labels[row] == (int)wmi) ? 1.0f : 0.0f;
        atomicAdd(&s_cnt[bin],  1.0f);
        atomicAdd(&s_conf[bin], conf);
        atomicAdd(&s_acc[bin],  acc);
    }
}

__global__ __launch_bounds__(THREADS, 2) void ece_fused_kernel(
    const float* __restrict__ logits,
    const int* __restrict__ labels,
    int n_rows,
    float* __restrict__ out)
{
    __shared__ float s_cnt[NBINS];
    __shared__ float s_conf[NBINS];
    __shared__ float s_acc[NBINS];
    __shared__ bool  s_is_last;

    const int tid  = threadIdx.x;
    const int lane = tid & 31;
    const int warp = tid >> 5;

    if (tid < NBINS) {
        s_cnt[tid]  = 0.0f;
        s_conf[tid] = 0.0f;
        s_acc[tid]  = 0.0f;
    }
    __syncthreads();

    const int total_warps = gridDim.x * WARPS_PER_BLOCK;
    int row = blockIdx.x * WARPS_PER_BLOCK + warp;

    // Software-pipelined double buffer: next row's 8 LDG.128 are in flight
    // while the current row's max/exp math runs.
    float4 A[8], B[8];
    bool valid = row < n_rows;
    if (valid) load_row(A, logits, row, lane);
    while (valid) {
        int nrow = row + total_warps;
        bool nvalid = nrow < n_rows;
        if (nvalid) load_row(B, logits, nrow, lane);
        process_row(A, labels, row, lane, s_cnt, s_conf, s_acc);
        row = nrow; valid = nvalid;
        if (!valid) break;

        nrow = row + total_warps;
        nvalid = nrow < n_rows;
        if (nvalid) load_row(A, logits, nrow, lane);
        process_row(B, labels, row, lane, s_cnt, s_conf, s_acc);
        row = nrow; valid = nvalid;
    }

    __syncthreads();
    if (tid < NBINS) {
        float c = s_cnt[tid];
        if (c != 0.0f) {
            atomicAdd(&g_cnt[tid],  (double)c);
            atomicAdd(&g_conf[tid], (double)s_conf[tid]);
            atomicAdd(&g_acc[tid],  (double)s_acc[tid]);
        }
    }

    // Last-block-done: fence our global atomics, then take a ticket.
    __threadfence();
    __syncthreads();
    if (tid == 0) {
        unsigned int t = atomicAdd(&g_ticket, 1u);
        s_is_last = (t == gridDim.x - 1);
    }
    __syncthreads();

    if (s_is_last && warp == 0) {
        double term_ece = 0.0, term_acc = 0.0;
        if (lane < NBINS) {
            double cnt = g_cnt[lane];
            if (cnt > 0.0) {
                double prop = cnt / (double)n_rows;
                double avg_conf = g_conf[lane] / cnt;
                double avg_acc  = g_acc[lane]  / cnt;
                term_ece = fabs(avg_conf - avg_acc) * prop;
                term_acc = avg_acc * prop;
            }
            // Reset accumulators for the next graph replay.
            g_cnt[lane]  = 0.0;
            g_conf[lane] = 0.0;
            g_acc[lane]  = 0.0;
        }
        #pragma unroll
        for (int off = 16; off; off >>= 1) {
            term_ece += __shfl_xor_sync(0xffffffffu, term_ece, off);
            term_acc += __shfl_xor_sync(0xffffffffu, term_acc, off);
        }
        if (lane == 0) {
            out[0] = (float)(term_ece * 100.0);
            out[1] = (float)(term_acc * 100.0);
            g_ticket = 0;
        }
    }
}

extern "C" void kernel_launch(void* const* d_in, const int* in_sizes, int n_in,
                              void* d_out, int out_size) {
    const float* logits = (const float*)d_in[0];
    const int*   labels = (const int*)d_in[1];
    float* out = (float*)d_out;

    int n_rows = in_sizes[1];  // labels element count = N

    ece_fused_kernel<<<GRID_BLOCKS, THREADS>>>(logits, labels, n_rows, out);
}